// round 11
// baseline (speedup 1.0000x reference)
#include <cuda_runtime.h>
#include <cstdint>
#include <cstddef>

#define BB 32
#define NN 25200
#define NCC 20
#define KK 1024
#define MAXDET 300
#define CONF_T 0.001f
#define IOU_T 0.45f

// ---------- scratch (static device allocations; no cudaMalloc) ----------
__device__ float              g_conf[BB * NN];
__device__ unsigned char      g_lab [BB * NN];
__device__ float4             g_tbox[BB * KK];
__device__ float              g_tsc [BB * KK];
__device__ int                g_tlb [BB * KK];
__device__ unsigned           g_msk [BB * KK * 32];  // TRANSPOSED mask: [b][w*1024+j]
__device__ unsigned           g_hist[BB * 2048];     // 13-bit hist; zero at load; re-zeroed by k_sortemit
__device__ int                g_cnt [BB];            // candidate counters; re-zeroed by k_sortemit
__device__ unsigned long long g_cand[BB * 8192];     // unsorted candidate keys

// ---------- kernel A: scores + argmax labels + fused global histogram (full-chip DRAM stream) ----------
__global__ void k_score(const float* __restrict__ pred) {
    __shared__ float s[256 * 25];
    size_t base4 = (size_t)blockIdx.x * 1600;           // 6400 floats = 1600 float4
    const float4* p4 = (const float4*)pred + base4;
    float4* s4 = (float4*)s;
    for (int k = threadIdx.x; k < 1600; k += 256) s4[k] = p4[k];
    __syncthreads();
    const float* row = s + threadIdx.x * 25;
    float obj  = row[4];
    float best = row[5];
    int   bl   = 0;
#pragma unroll
    for (int c = 1; c < NCC; c++) {
        float v = row[5 + c];
        if (v > best) { best = v; bl = c; }             // first-max like jnp.argmax
    }
    float conf = __fmul_rn(obj, best);
    int r = blockIdx.x * 256 + threadIdx.x;
    g_conf[r] = conf;
    g_lab[r]  = (unsigned char)bl;
    if (conf > CONF_T) {
        int b = r / NN;
        atomicAdd(&g_hist[b * 2048 + (__float_as_uint(conf) >> 19)], 1u);  // REDG, hidden under stream
    }
}

// ---------- kernel B1a: grid-wide candidate collection (order-free; key embeds tiebreak) ----------
// grid (25, BB): block (seg, b) tests rows seg*1024..seg*1024+1023. Each block redundantly
// computes the batch threshold T from g_hist (cheap L2 reads), then scatters qualifying keys.
__global__ void __launch_bounds__(1024, 1) k_collect() {
    __shared__ unsigned h[2048];
    __shared__ unsigned wsc[64];
    __shared__ int ctrl[4];
    int b = blockIdx.y, seg = blockIdx.x;
    int tid = threadIdx.x;
    int lane = tid & 31, wid = tid >> 5;

    h[tid] = g_hist[b * 2048 + tid];
    h[tid + 1024] = g_hist[b * 2048 + tid + 1024];
    if (tid == 0) ctrl[0] = -1;
    __syncthreads();

    // pair-suffix scan (proven R10 logic) -> T = max bucket with suffix >= KK
    unsigned ps = h[2 * tid] + h[2 * tid + 1];
    unsigned s = ps;
#pragma unroll
    for (int off = 1; off < 32; off <<= 1) {
        unsigned v = __shfl_down_sync(0xffffffffu, s, off);
        if (lane + off < 32) s += v;
    }
    if (lane == 0) wsc[wid] = s;
    __syncthreads();
    if (wid == 0) {
        unsigned t = wsc[lane];
#pragma unroll
        for (int off = 1; off < 32; off <<= 1) {
            unsigned v = __shfl_down_sync(0xffffffffu, t, off);
            if (lane + off < 32) t += v;
        }
        unsigned tail = __shfl_down_sync(0xffffffffu, t, 1);
        if (lane == 31) tail = 0;
        wsc[32 + lane] = tail;
    }
    __syncthreads();
    unsigned S = s + wsc[32 + wid];
    unsigned Snext = S - ps;
    if (Snext + h[2 * tid + 1] >= KK) atomicMax(&ctrl[0], 2 * tid + 1);
    else if (S >= KK)                 atomicMax(&ctrl[0], 2 * tid);
    __syncthreads();
    unsigned T = (unsigned)(ctrl[0] < 0 ? 0 : ctrl[0]);

    int n = seg * 1024 + tid;
    float v = (n < NN) ? g_conf[(size_t)b * NN + n] : -1.0f;
    if (v > CONF_T) {
        unsigned bits = __float_as_uint(v);
        if ((bits >> 19) >= T) {
            int p = atomicAdd(&g_cnt[b], 1);
            if (p < 8192)
                g_cand[b * 8192 + p] = ((unsigned long long)bits << 32)
                                     | (unsigned long long)(0xFFFFFFFFu - (unsigned)n);
        }
    }
}

// ---------- kernel B1b: sort candidates + emit top-1024 (+ scratch re-zero for graph replay) ----------
__global__ void __launch_bounds__(1024, 1) k_sortemit(const float* __restrict__ pred) {
    extern __shared__ unsigned sh[];
    unsigned long long* cand = (unsigned long long*)sh;  // 8192 keys (64 KB)

    int b = blockIdx.x;
    int tid = threadIdx.x;

    int cnt = g_cnt[b]; if (cnt > 8192) cnt = 8192;

    if (cnt <= 2048) {
        // load + pad to 2048
        for (int p = tid; p < 2048; p += 1024)
            cand[p] = (p < cnt) ? g_cand[b * 8192 + p] : 0ull;
        __syncthreads();
        // ---- hybrid bitonic sort of 2048 keys, descending ----
        unsigned long long va = cand[tid], vb = cand[tid + 1024];
#pragma unroll
        for (int k = 2; k <= 32; k <<= 1) {
#pragma unroll
            for (int j = k >> 1; j >= 1; j >>= 1) {
                bool lower = (tid & j) == 0;
                {
                    unsigned long long pa = __shfl_xor_sync(0xffffffffu, va, j);
                    bool dir = (tid & k) == 0;
                    va = (((dir == lower) ? (va > pa) : (va < pa))) ? va : pa;
                }
                {
                    unsigned long long pb2 = __shfl_xor_sync(0xffffffffu, vb, j);
                    bool dir = ((tid + 1024) & k) == 0;
                    vb = (((dir == lower) ? (vb > pb2) : (vb < pb2))) ? vb : pb2;
                }
            }
        }
        cand[tid] = va; cand[tid + 1024] = vb;
        __syncthreads();
        for (int k = 64; k <= 2048; k <<= 1) {
            for (int j = k >> 1; j >= 32; j >>= 1) {
                for (int t2 = tid; t2 < 2048; t2 += 1024) {
                    int ixj = t2 ^ j;
                    if (ixj > t2) {
                        unsigned long long a = cand[t2], c2 = cand[ixj];
                        if (((t2 & k) == 0) ? (a < c2) : (a > c2)) { cand[t2] = c2; cand[ixj] = a; }
                    }
                }
                __syncthreads();
            }
            va = cand[tid]; vb = cand[tid + 1024];
#pragma unroll
            for (int j = 16; j >= 1; j >>= 1) {
                bool lower = (tid & j) == 0;
                {
                    unsigned long long pa = __shfl_xor_sync(0xffffffffu, va, j);
                    bool dir = (tid & k) == 0;
                    va = (((dir == lower) ? (va > pa) : (va < pa))) ? va : pa;
                }
                {
                    unsigned long long pb2 = __shfl_xor_sync(0xffffffffu, vb, j);
                    bool dir = ((tid + 1024) & k) == 0;
                    vb = (((dir == lower) ? (vb > pb2) : (vb < pb2))) ? vb : pb2;
                }
            }
            cand[tid] = va; cand[tid + 1024] = vb;
            __syncthreads();
        }
    } else {
        // ---- generic fallback (rare): plain smem bitonic up to 8192 ----
        int n2 = 2048; while (n2 < cnt) n2 <<= 1;
        for (int p = tid; p < n2; p += 1024)
            cand[p] = (p < cnt) ? g_cand[b * 8192 + p] : 0ull;
        __syncthreads();
        for (int k = 2; k <= n2; k <<= 1) {
            for (int j = k >> 1; j > 0; j >>= 1) {
                for (int t2 = tid; t2 < n2; t2 += 1024) {
                    int ixj = t2 ^ j;
                    if (ixj > t2) {
                        unsigned long long a = cand[t2], c2 = cand[ixj];
                        if (((t2 & k) == 0) ? (a < c2) : (a > c2)) { cand[t2] = c2; cand[ixj] = a; }
                    }
                }
                __syncthreads();
            }
        }
    }

    // ---- emit top-1024: score, label, xywh->xyxy (non-fused to match ref) ----
    {
        unsigned long long key = cand[tid];
        unsigned sbits = (unsigned)(key >> 32);
        float score; int n;
        if (sbits) { score = __uint_as_float(sbits); n = (int)(0xFFFFFFFFu - (unsigned)key); }
        else       { score = -1.0f; n = 0; }
        const float* pr = pred + ((size_t)b * NN + n) * 25;
        float x = pr[0], y = pr[1], w = pr[2], h2 = pr[3];
        float hw = __fmul_rn(w, 0.5f), hh = __fmul_rn(h2, 0.5f);
        int idx = b * KK + tid;
        g_tbox[idx] = make_float4(__fsub_rn(x, hw), __fsub_rn(y, hh),
                                  __fadd_rn(x, hw), __fadd_rn(y, hh));
        g_tsc[idx]  = score;
        g_tlb[idx]  = (int)g_lab[(size_t)b * NN + n];
    }

    // ---- re-zero scratch so every graph replay sees clean state (identical work) ----
    g_hist[b * 2048 + tid] = 0;
    g_hist[b * 2048 + tid + 1024] = 0;
    if (tid == 0) g_cnt[b] = 0;
}

// ---------- kernel B2: pairwise IoU -> TRANSPOSED mask, load-balanced strip pairing ----------
__global__ void k_iou() {
    __shared__ float ix1[64], iy1[64], ix2[64], iy2[64], iar[64];
    int b = blockIdx.y, wp = blockIdx.x, tid = threadIdx.x;

    if (tid < 64) {
        int strip = (tid < 32) ? wp : (31 - wp);
        int i = strip * 32 + (tid & 31);
        float4 bx = g_tbox[b * KK + i];
        float off = __fmul_rn((float)g_tlb[b * KK + i], 4096.0f);
        // offsets applied BEFORE area: fp32 quantization at +label*4096 must match ref
        float ox1 = __fadd_rn(bx.x, off), oy1 = __fadd_rn(bx.y, off);
        float ox2 = __fadd_rn(bx.z, off), oy2 = __fadd_rn(bx.w, off);
        ix1[tid] = ox1; iy1[tid] = oy1; ix2[tid] = ox2; iy2[tid] = oy2;
        iar[tid] = __fmul_rn(__fsub_rn(ox2, ox1), __fsub_rn(oy2, oy1));
    }
    __syncthreads();

#pragma unroll
    for (int half = 0; half < 2; half++) {
        int w = half ? (31 - wp) : wp;
        int sbase = half * 32;
        for (int j = 32 * w + tid; j < 1024; j += 256) {
            float4 bx = g_tbox[b * KK + j];
            float off = __fmul_rn((float)g_tlb[b * KK + j], 4096.0f);
            float jx1 = __fadd_rn(bx.x, off), jy1 = __fadd_rn(bx.y, off);
            float jx2 = __fadd_rn(bx.z, off), jy2 = __fadd_rn(bx.w, off);
            float aj  = __fmul_rn(__fsub_rn(jx2, jx1), __fsub_rn(jy2, jy1));
            int top = j - 32 * w; if (top > 32) top = 32;
            unsigned bits = 0;
            for (int bi = 0; bi < top; bi++) {   // smem broadcast reads
                float ltx = fmaxf(jx1, ix1[sbase + bi]), lty = fmaxf(jy1, iy1[sbase + bi]);
                float rbx = fminf(jx2, ix2[sbase + bi]), rby = fminf(jy2, iy2[sbase + bi]);
                float ww = fmaxf(__fsub_rn(rbx, ltx), 0.0f);
                float hh = fmaxf(__fsub_rn(rby, lty), 0.0f);
                float inter = __fmul_rn(ww, hh);
                float den = __fadd_rn(__fsub_rn(__fadd_rn(iar[sbase + bi], aj), inter), 1e-9f);
                // margin compare: exact decision without div except in a ~1e-4 band
                float d = __fsub_rn(inter, __fmul_rn(IOU_T, den));
                float marg = __fmul_rn(den, 1e-4f);
                bool sup;
                if (fabsf(d) <= marg) sup = (inter / den) > IOU_T;   // rare exact IEEE path
                else                  sup = d > 0.0f;
                if (sup) bits |= (1u << bi);
            }
            if (top > 0) g_msk[(size_t)b * 32768 + w * 1024 + j] = bits;  // coalesced over j
        }
    }
}

// ---------- kernel B3: Jacobi-fixpoint greedy NMS + clip/filter + top-300 compaction ----------
__global__ void __launch_bounds__(1024, 1) k_nms(const int* __restrict__ imw, const int* __restrict__ imh,
                      float* __restrict__ out) {
    extern __shared__ unsigned sh[];
    unsigned* cm    = sh;                    // 32768 words, [w][j] (lower triangle valid)
    unsigned* kwsA  = sh + 32768;            // 32
    unsigned* kwsB  = sh + 32800;            // 32
    unsigned* wcnt  = sh + 32832;            // 32
    unsigned* wbal  = sh + 32864;            // 32
    int*      ctrl  = (int*)(sh + 32896);    // 4
    float4*   cbox  = (float4*)(sh + 32900); // 300 (32900*4 % 16 == 0)
    float*    cscore = (float*)(cbox + MAXDET);
    int*      clabel = (int*)(cscore + MAXDET);

    int b = blockIdx.x, tid = threadIdx.x;
    int lane = tid & 31, wid = tid >> 5;

    // vectorized lower-triangle mask load (4-aligned j groups share the same w, j>>5)
    for (int base = tid * 4; base < 32768; base += 4096) {
        int w = base >> 10, j0 = base & 1023;
        if (w <= (j0 >> 5))
            *(uint4*)(cm + base) = *(const uint4*)(g_msk + (size_t)b * 32768 + base);
    }
    float score = g_tsc[b * KK + tid];
    bool cnd = score > CONF_T;
    unsigned cbal = __ballot_sync(0xffffffffu, cnd);
    if (lane == 0) kwsA[wid] = cbal;
    __syncthreads();

    // Jacobi fixpoint: keep[j] = cand[j] & !exists(i<j: sup(i,j) & keep[i])
    unsigned* cur = kwsA;
    unsigned* nxt = kwsB;
    unsigned mself = cm[wid * 1024 + tid] & ((1u << lane) - 1u);
    for (int it = 0; it < 1025; it++) {
        unsigned sup = mself & cur[wid];
        for (int w = 0; w < wid; w++)
            sup |= cm[w * 1024 + tid] & cur[w];  // conflict-free; cur[w] broadcast
        bool nk = cnd && (sup == 0u);
        unsigned nb = __ballot_sync(0xffffffffu, nk);
        if (lane == 0) nxt[wid] = nb;
        int changed = __syncthreads_or((int)(nb != cur[wid]));
        if (!changed) break;
        unsigned* t = cur; cur = nxt; nxt = t;
    }

    bool keep = (cur[wid] >> lane) & 1u;
    float fw = (float)(*imw), fh = (float)(*imh);
    float4 bx = g_tbox[b * KK + tid];
    float x1c = fminf(fmaxf(bx.x, 0.0f), fw);
    float y1c = fminf(fmaxf(bx.y, 0.0f), fh);
    float x2c = fminf(fmaxf(bx.z, 0.0f), fw);
    float y2c = fminf(fmaxf(bx.w, 0.0f), fh);
    float bw  = __fsub_rn(x2c, x1c);
    float bh2 = __fsub_rn(y2c, y1c);
    bool valid = keep && (bw > 0.0f) && (bh2 > 0.0f) && (bw >= 1.0f) && (bh2 >= 1.0f);

    unsigned vb = __ballot_sync(0xffffffffu, valid);
    if (lane == 0) { wcnt[wid] = __popc(vb); wbal[wid] = vb; }
    __syncthreads();
    if (tid == 0) {
        int acc2 = 0;
        for (int q = 0; q < 32; q++) { int c = wcnt[q]; wcnt[q] = acc2; acc2 += c; }
        ctrl[0] = acc2;
    }
    __syncthreads();
    if (valid) {
        int rank = wcnt[wid] + __popc(wbal[wid] & ((1u << lane) - 1u));
        if (rank < MAXDET) {
            cbox[rank]   = make_float4(x1c, y1c, x2c, y2c);
            cscore[rank] = score;
            clabel[rank] = g_tlb[b * KK + tid];
        }
    }
    __syncthreads();

    int total = ctrl[0]; if (total > MAXDET) total = MAXDET;
    if (tid < MAXDET) {
        float4 ob; float os, ol, ov;
        if (tid < total) { ob = cbox[tid]; os = cscore[tid]; ol = (float)clabel[tid]; ov = 1.0f; }
        else             { ob = make_float4(0, 0, 0, 0); os = 0.0f; ol = 0.0f; ov = 0.0f; }
        float* obox = out + ((size_t)b * MAXDET + tid) * 4;
        obox[0] = ob.x; obox[1] = ob.y; obox[2] = ob.z; obox[3] = ob.w;
        out[BB * MAXDET * 4 + b * MAXDET + tid] = os;   // det_scores
        out[BB * MAXDET * 5 + b * MAXDET + tid] = ol;   // det_labels (as f32)
        out[BB * MAXDET * 6 + b * MAXDET + tid] = ov;   // vm (as f32)
    }
}

extern "C" void kernel_launch(void* const* d_in, const int* in_sizes, int n_in,
                              void* d_out, int out_size) {
    const float* pred = (const float*)d_in[0];
    const int*   imh  = (const int*)d_in[1];
    const int*   imw  = (const int*)d_in[2];
    float* out = (float*)d_out;

    cudaFuncSetAttribute((const void*)k_sortemit,
                         cudaFuncAttributeMaxDynamicSharedMemorySize, 65536);
    cudaFuncSetAttribute((const void*)k_nms,
                         cudaFuncAttributeMaxDynamicSharedMemorySize, 138800);

    k_score<<<(BB * NN) / 256, 256>>>(pred);
    k_collect<<<dim3(25, BB), 1024>>>();
    k_sortemit<<<BB, 1024, 65536>>>(pred);
    k_iou<<<dim3(16, BB), 256>>>();
    k_nms<<<BB, 1024, 138800>>>(imw, imh, out);
}

// round 12
// speedup vs baseline: 1.1792x; 1.1792x over previous
#include <cuda_runtime.h>
#include <cstdint>
#include <cstddef>

#define BB 32
#define NN 25200
#define NCC 20
#define KK 1024
#define MAXDET 300
#define CONF_T 0.001f
#define IOU_T 0.45f

// ---------- scratch (static device allocations; no cudaMalloc) ----------
__device__ float         g_conf[BB * NN];
__device__ unsigned char g_lab [BB * NN];
__device__ float4        g_tbox[BB * KK];
__device__ float         g_tsc [BB * KK];
__device__ int           g_tlb [BB * KK];
__device__ unsigned      g_msk [BB * KK * 32];   // TRANSPOSED mask: [b][w*1024+j], bit bi => i=32w+bi suppresses j (i<j)

// ---------- kernel A: scores + argmax labels (grid-parallel DRAM stream; 2 sub-launches) ----------
__global__ void k_score(const float* __restrict__ pred, int blockOff) {
    __shared__ float s[256 * 25];
    int blk = blockOff + blockIdx.x;
    size_t base4 = (size_t)blk * 1600;                  // 6400 floats = 1600 float4
    const float4* p4 = (const float4*)pred + base4;
    float4* s4 = (float4*)s;
    for (int k = threadIdx.x; k < 1600; k += 256) s4[k] = p4[k];
    __syncthreads();
    const float* row = s + threadIdx.x * 25;
    float obj  = row[4];
    float best = row[5];
    int   bl   = 0;
#pragma unroll
    for (int c = 1; c < NCC; c++) {
        float v = row[5 + c];
        if (v > best) { best = v; bl = c; }             // first-max like jnp.argmax
    }
    float conf = __fmul_rn(obj, best);
    size_t r = (size_t)blk * 256 + threadIdx.x;
    g_conf[r] = conf;
    g_lab[r]  = (unsigned char)bl;
}

// ---------- kernel B1: exact stable top-1024 per batch (R10 monolith, register-batched) ----------
__global__ void __launch_bounds__(1024, 1) k_topk(const float* __restrict__ pred) {
    extern __shared__ unsigned sh[];
    unsigned long long* cand = (unsigned long long*)sh;  // 8192 keys (64 KB)
    unsigned* h    = sh + 16384;          // 2048 bucket counts (bits>>19)
    int*      ctrl = (int*)(sh + 18432);  // 16: [0]=T(bucket) [2]=cnt
    unsigned* wsc  = sh + 18448;          // 64: warp totals + tails

    int b = blockIdx.x;
    int tid = threadIdx.x;
    int lane = tid & 31, wid = tid >> 5;
    const float* sc = g_conf + (size_t)b * NN;

    h[tid] = 0; h[tid + 1024] = 0;
    if (tid < 16) ctrl[tid] = (tid == 0) ? -1 : 0;
    __syncthreads();

    // batched load: all 25 conf values front-loaded (MLP ~25)
    float creg[25];
#pragma unroll
    for (int c = 0; c < 25; c++) {
        int n = c * 1024 + tid;
        creg[c] = (n < NN) ? sc[n] : -1.0f;
    }
#pragma unroll
    for (int c = 0; c < 25; c++) {
        float v = creg[c];
        if (v > CONF_T) atomicAdd(&h[__float_as_uint(v) >> 19], 1u);
    }
    __syncthreads();

    // threshold: suffix-scan over 1024 bucket-pairs via warp shuffles
    unsigned ps = h[2 * tid] + h[2 * tid + 1];
    unsigned s = ps;
#pragma unroll
    for (int off = 1; off < 32; off <<= 1) {
        unsigned v = __shfl_down_sync(0xffffffffu, s, off);
        if (lane + off < 32) s += v;
    }
    if (lane == 0) wsc[wid] = s;
    __syncthreads();
    if (wid == 0) {
        unsigned t = wsc[lane];
#pragma unroll
        for (int off = 1; off < 32; off <<= 1) {
            unsigned v = __shfl_down_sync(0xffffffffu, t, off);
            if (lane + off < 32) t += v;
        }
        unsigned tail = __shfl_down_sync(0xffffffffu, t, 1);
        if (lane == 31) tail = 0;
        wsc[32 + lane] = tail;
    }
    __syncthreads();
    unsigned S = s + wsc[32 + wid];
    unsigned Snext = S - ps;
    if (Snext + h[2 * tid + 1] >= KK) atomicMax(&ctrl[0], 2 * tid + 1);
    else if (S >= KK)                 atomicMax(&ctrl[0], 2 * tid);
    __syncthreads();
    unsigned T = (unsigned)(ctrl[0] < 0 ? 0 : ctrl[0]);

    // collect candidates straight from registers
#pragma unroll
    for (int c = 0; c < 25; c++) {
        float v = creg[c];
        if (v > CONF_T) {
            unsigned bits = __float_as_uint(v);
            if ((bits >> 19) >= T) {
                int p = atomicAdd(&ctrl[2], 1);
                if (p < 8192) {
                    unsigned n = (unsigned)(c * 1024 + tid);
                    cand[p] = ((unsigned long long)bits << 32)
                            | (unsigned long long)(0xFFFFFFFFu - n);
                }
            }
        }
    }
    __syncthreads();
    int cnt = ctrl[2]; if (cnt > 8192) cnt = 8192;

    if (cnt <= 2048) {
        // hybrid bitonic sort of 2048 keys, descending
        for (int p = cnt + tid; p < 2048; p += 1024) cand[p] = 0ull;
        __syncthreads();
        unsigned long long va = cand[tid], vb = cand[tid + 1024];
#pragma unroll
        for (int k = 2; k <= 32; k <<= 1) {
#pragma unroll
            for (int j = k >> 1; j >= 1; j >>= 1) {
                bool lower = (tid & j) == 0;
                {
                    unsigned long long pa = __shfl_xor_sync(0xffffffffu, va, j);
                    bool dir = (tid & k) == 0;
                    va = (((dir == lower) ? (va > pa) : (va < pa))) ? va : pa;
                }
                {
                    unsigned long long pb2 = __shfl_xor_sync(0xffffffffu, vb, j);
                    bool dir = ((tid + 1024) & k) == 0;
                    vb = (((dir == lower) ? (vb > pb2) : (vb < pb2))) ? vb : pb2;
                }
            }
        }
        cand[tid] = va; cand[tid + 1024] = vb;
        __syncthreads();
        for (int k = 64; k <= 2048; k <<= 1) {
            for (int j = k >> 1; j >= 32; j >>= 1) {
                for (int t2 = tid; t2 < 2048; t2 += 1024) {
                    int ixj = t2 ^ j;
                    if (ixj > t2) {
                        unsigned long long a = cand[t2], c2 = cand[ixj];
                        if (((t2 & k) == 0) ? (a < c2) : (a > c2)) { cand[t2] = c2; cand[ixj] = a; }
                    }
                }
                __syncthreads();
            }
            va = cand[tid]; vb = cand[tid + 1024];
#pragma unroll
            for (int j = 16; j >= 1; j >>= 1) {
                bool lower = (tid & j) == 0;
                {
                    unsigned long long pa = __shfl_xor_sync(0xffffffffu, va, j);
                    bool dir = (tid & k) == 0;
                    va = (((dir == lower) ? (va > pa) : (va < pa))) ? va : pa;
                }
                {
                    unsigned long long pb2 = __shfl_xor_sync(0xffffffffu, vb, j);
                    bool dir = ((tid + 1024) & k) == 0;
                    vb = (((dir == lower) ? (vb > pb2) : (vb < pb2))) ? vb : pb2;
                }
            }
            cand[tid] = va; cand[tid + 1024] = vb;
            __syncthreads();
        }
    } else {
        // generic fallback (rare): plain smem bitonic up to 8192
        int n2 = 2048; while (n2 < cnt) n2 <<= 1;
        for (int p = cnt + tid; p < n2; p += 1024) cand[p] = 0ull;
        __syncthreads();
        for (int k = 2; k <= n2; k <<= 1) {
            for (int j = k >> 1; j > 0; j >>= 1) {
                for (int t2 = tid; t2 < n2; t2 += 1024) {
                    int ixj = t2 ^ j;
                    if (ixj > t2) {
                        unsigned long long a = cand[t2], c2 = cand[ixj];
                        if (((t2 & k) == 0) ? (a < c2) : (a > c2)) { cand[t2] = c2; cand[ixj] = a; }
                    }
                }
                __syncthreads();
            }
        }
    }

    // emit top-1024: score, label, xywh->xyxy (non-fused to match ref)
    {
        unsigned long long key = cand[tid];
        unsigned sbits = (unsigned)(key >> 32);
        float score; int n;
        if (sbits) { score = __uint_as_float(sbits); n = (int)(0xFFFFFFFFu - (unsigned)key); }
        else       { score = -1.0f; n = 0; }
        const float* pr = pred + ((size_t)b * NN + n) * 25;
        float x = pr[0], y = pr[1], w = pr[2], h2 = pr[3];
        float hw = __fmul_rn(w, 0.5f), hh = __fmul_rn(h2, 0.5f);
        int idx = b * KK + tid;
        g_tbox[idx] = make_float4(__fsub_rn(x, hw), __fsub_rn(y, hh),
                                  __fadd_rn(x, hw), __fadd_rn(y, hh));
        g_tsc[idx]  = score;
        g_tlb[idx]  = (int)g_lab[(size_t)b * NN + n];
    }
}

// ---------- kernel B2: pairwise IoU -> TRANSPOSED mask, strip-paired + j-split (1024 blocks) ----------
// Block (bx, b): wp = bx>>1 pairs strips (wp, 31-wp) [balanced 1056 j's], jh = bx&1 takes
// alternating 256-wide j-chunks (stride 512). Union over jh is exact and disjoint.
__global__ void k_iou() {
    __shared__ float ix1[64], iy1[64], ix2[64], iy2[64], iar[64];
    int b = blockIdx.y, bx = blockIdx.x, tid = threadIdx.x;
    int wp = bx >> 1, jh = bx & 1;

    if (tid < 64) {
        int strip = (tid < 32) ? wp : (31 - wp);
        int i = strip * 32 + (tid & 31);
        float4 bxv = g_tbox[b * KK + i];
        float off = __fmul_rn((float)g_tlb[b * KK + i], 4096.0f);
        // offsets applied BEFORE area: fp32 quantization at +label*4096 must match ref
        float ox1 = __fadd_rn(bxv.x, off), oy1 = __fadd_rn(bxv.y, off);
        float ox2 = __fadd_rn(bxv.z, off), oy2 = __fadd_rn(bxv.w, off);
        ix1[tid] = ox1; iy1[tid] = oy1; ix2[tid] = ox2; iy2[tid] = oy2;
        iar[tid] = __fmul_rn(__fsub_rn(ox2, ox1), __fsub_rn(oy2, oy1));
    }
    __syncthreads();

#pragma unroll
    for (int half = 0; half < 2; half++) {
        int w = half ? (31 - wp) : wp;
        int sbase = half * 32;
        for (int j = 32 * w + jh * 256 + tid; j < 1024; j += 512) {
            float4 bxv = g_tbox[b * KK + j];
            float off = __fmul_rn((float)g_tlb[b * KK + j], 4096.0f);
            float jx1 = __fadd_rn(bxv.x, off), jy1 = __fadd_rn(bxv.y, off);
            float jx2 = __fadd_rn(bxv.z, off), jy2 = __fadd_rn(bxv.w, off);
            float aj  = __fmul_rn(__fsub_rn(jx2, jx1), __fsub_rn(jy2, jy1));
            int top = j - 32 * w; if (top > 32) top = 32;
            unsigned bits = 0;
            for (int bi = 0; bi < top; bi++) {   // smem broadcast reads
                float ltx = fmaxf(jx1, ix1[sbase + bi]), lty = fmaxf(jy1, iy1[sbase + bi]);
                float rbx = fminf(jx2, ix2[sbase + bi]), rby = fminf(jy2, iy2[sbase + bi]);
                float ww = fmaxf(__fsub_rn(rbx, ltx), 0.0f);
                float hh = fmaxf(__fsub_rn(rby, lty), 0.0f);
                float inter = __fmul_rn(ww, hh);
                float den = __fadd_rn(__fsub_rn(__fadd_rn(iar[sbase + bi], aj), inter), 1e-9f);
                // margin compare: exact decision without div except in a ~1e-4 band
                float d = __fsub_rn(inter, __fmul_rn(IOU_T, den));
                float marg = __fmul_rn(den, 1e-4f);
                bool sup;
                if (fabsf(d) <= marg) sup = (inter / den) > IOU_T;   // rare exact IEEE path
                else                  sup = d > 0.0f;
                if (sup) bits |= (1u << bi);
            }
            if (top > 0) g_msk[(size_t)b * 32768 + w * 1024 + j] = bits;  // coalesced over j
        }
    }
}

// ---------- kernel B3: Jacobi-fixpoint greedy NMS + clip/filter + top-300 compaction ----------
__global__ void __launch_bounds__(1024, 1) k_nms(const int* __restrict__ imw, const int* __restrict__ imh,
                      float* __restrict__ out) {
    extern __shared__ unsigned sh[];
    unsigned* cm    = sh;                    // 32768 words, [w][j] (lower triangle valid)
    unsigned* kwsA  = sh + 32768;            // 32
    unsigned* kwsB  = sh + 32800;            // 32
    unsigned* wcnt  = sh + 32832;            // 32
    unsigned* wbal  = sh + 32864;            // 32
    int*      ctrl  = (int*)(sh + 32896);    // 4
    float4*   cbox  = (float4*)(sh + 32900); // 300 (32900*4 % 16 == 0)
    float*    cscore = (float*)(cbox + MAXDET);
    int*      clabel = (int*)(cscore + MAXDET);

    int b = blockIdx.x, tid = threadIdx.x;
    int lane = tid & 31, wid = tid >> 5;

    // vectorized lower-triangle mask load (4-aligned j groups share the same w, j>>5)
    for (int base = tid * 4; base < 32768; base += 4096) {
        int w = base >> 10, j0 = base & 1023;
        if (w <= (j0 >> 5))
            *(uint4*)(cm + base) = *(const uint4*)(g_msk + (size_t)b * 32768 + base);
    }
    float score = g_tsc[b * KK + tid];
    bool cnd = score > CONF_T;
    unsigned cbal = __ballot_sync(0xffffffffu, cnd);
    if (lane == 0) kwsA[wid] = cbal;
    __syncthreads();

    // Jacobi fixpoint: keep[j] = cand[j] & !exists(i<j: sup(i,j) & keep[i])
    unsigned* cur = kwsA;
    unsigned* nxt = kwsB;
    unsigned mself = cm[wid * 1024 + tid] & ((1u << lane) - 1u);
    for (int it = 0; it < 1025; it++) {
        unsigned sup = mself & cur[wid];
        for (int w = 0; w < wid; w++)
            sup |= cm[w * 1024 + tid] & cur[w];  // conflict-free; cur[w] broadcast
        bool nk = cnd && (sup == 0u);
        unsigned nb = __ballot_sync(0xffffffffu, nk);
        if (lane == 0) nxt[wid] = nb;
        int changed = __syncthreads_or((int)(nb != cur[wid]));
        if (!changed) break;
        unsigned* t = cur; cur = nxt; nxt = t;
    }

    bool keep = (cur[wid] >> lane) & 1u;
    float fw = (float)(*imw), fh = (float)(*imh);
    float4 bx = g_tbox[b * KK + tid];
    float x1c = fminf(fmaxf(bx.x, 0.0f), fw);
    float y1c = fminf(fmaxf(bx.y, 0.0f), fh);
    float x2c = fminf(fmaxf(bx.z, 0.0f), fw);
    float y2c = fminf(fmaxf(bx.w, 0.0f), fh);
    float bw  = __fsub_rn(x2c, x1c);
    float bh2 = __fsub_rn(y2c, y1c);
    bool valid = keep && (bw > 0.0f) && (bh2 > 0.0f) && (bw >= 1.0f) && (bh2 >= 1.0f);

    unsigned vb = __ballot_sync(0xffffffffu, valid);
    if (lane == 0) { wcnt[wid] = __popc(vb); wbal[wid] = vb; }
    __syncthreads();
    if (tid == 0) {
        int acc2 = 0;
        for (int q = 0; q < 32; q++) { int c = wcnt[q]; wcnt[q] = acc2; acc2 += c; }
        ctrl[0] = acc2;
    }
    __syncthreads();
    if (valid) {
        int rank = wcnt[wid] + __popc(wbal[wid] & ((1u << lane) - 1u));
        if (rank < MAXDET) {
            cbox[rank]   = make_float4(x1c, y1c, x2c, y2c);
            cscore[rank] = score;
            clabel[rank] = g_tlb[b * KK + tid];
        }
    }
    __syncthreads();

    int total = ctrl[0]; if (total > MAXDET) total = MAXDET;
    if (tid < MAXDET) {
        float4 ob; float os, ol, ov;
        if (tid < total) { ob = cbox[tid]; os = cscore[tid]; ol = (float)clabel[tid]; ov = 1.0f; }
        else             { ob = make_float4(0, 0, 0, 0); os = 0.0f; ol = 0.0f; ov = 0.0f; }
        float* obox = out + ((size_t)b * MAXDET + tid) * 4;
        obox[0] = ob.x; obox[1] = ob.y; obox[2] = ob.z; obox[3] = ob.w;
        out[BB * MAXDET * 4 + b * MAXDET + tid] = os;   // det_scores
        out[BB * MAXDET * 5 + b * MAXDET + tid] = ol;   // det_labels (as f32)
        out[BB * MAXDET * 6 + b * MAXDET + tid] = ov;   // vm (as f32)
    }
}

extern "C" void kernel_launch(void* const* d_in, const int* in_sizes, int n_in,
                              void* d_out, int out_size) {
    const float* pred = (const float*)d_in[0];
    const int*   imh  = (const int*)d_in[1];
    const int*   imw  = (const int*)d_in[2];
    float* out = (float*)d_out;

    cudaFuncSetAttribute((const void*)k_topk,
                         cudaFuncAttributeMaxDynamicSharedMemorySize, 74048);
    cudaFuncSetAttribute((const void*)k_nms,
                         cudaFuncAttributeMaxDynamicSharedMemorySize, 138800);

    // 2-way k_score split keeps total work identical and places k_iou at the
    // profiler's capture slot (#4) to verify the occupancy fix next round.
    k_score<<<1575, 256>>>(pred, 0);
    k_score<<<1575, 256>>>(pred, 1575);
    k_topk<<<BB, 1024, 74048>>>(pred);
    k_iou<<<dim3(32, BB), 256>>>();
    k_nms<<<BB, 1024, 138800>>>(imw, imh, out);
}

// round 13
// speedup vs baseline: 1.2061x; 1.0228x over previous
#include <cuda_runtime.h>
#include <cstdint>
#include <cstddef>

#define BB 32
#define NN 25200
#define NCC 20
#define KK 1024
#define MAXDET 300
#define CONF_T 0.001f
#define IOU_T 0.45f

// ---------- scratch (static device allocations; no cudaMalloc) ----------
__device__ float         g_conf[BB * NN];
__device__ unsigned char g_lab [BB * NN];
__device__ float4        g_tbox[BB * KK];
__device__ float         g_tsc [BB * KK];
__device__ int           g_tlb [BB * KK];
__device__ unsigned      g_msk [BB * KK * 32];   // TRANSPOSED mask: [b][w*1024+j], bit bi => i=32w+bi suppresses j (i<j)

// ---------- kernel A: scores + argmax labels (grid-parallel DRAM stream; 2 sub-launches) ----------
__global__ void k_score(const float* __restrict__ pred, int blockOff) {
    __shared__ float s[256 * 25];
    int blk = blockOff + blockIdx.x;
    size_t base4 = (size_t)blk * 1600;                  // 6400 floats = 1600 float4
    const float4* p4 = (const float4*)pred + base4;
    float4* s4 = (float4*)s;
    for (int k = threadIdx.x; k < 1600; k += 256) s4[k] = p4[k];
    __syncthreads();
    const float* row = s + threadIdx.x * 25;
    float obj  = row[4];
    float best = row[5];
    int   bl   = 0;
#pragma unroll
    for (int c = 1; c < NCC; c++) {
        float v = row[5 + c];
        if (v > best) { best = v; bl = c; }             // first-max like jnp.argmax
    }
    float conf = __fmul_rn(obj, best);
    size_t r = (size_t)blk * 256 + threadIdx.x;
    g_conf[r] = conf;
    g_lab[r]  = (unsigned char)bl;
}

// ---------- kernel B1: exact stable top-1024 per batch (R10 monolith, register-batched) ----------
__global__ void __launch_bounds__(1024, 1) k_topk(const float* __restrict__ pred) {
    extern __shared__ unsigned sh[];
    unsigned long long* cand = (unsigned long long*)sh;  // 8192 keys (64 KB)
    unsigned* h    = sh + 16384;          // 2048 bucket counts (bits>>19)
    int*      ctrl = (int*)(sh + 18432);  // 16: [0]=T(bucket) [2]=cnt
    unsigned* wsc  = sh + 18448;          // 64: warp totals + tails

    int b = blockIdx.x;
    int tid = threadIdx.x;
    int lane = tid & 31, wid = tid >> 5;
    const float* sc = g_conf + (size_t)b * NN;

    h[tid] = 0; h[tid + 1024] = 0;
    if (tid < 16) ctrl[tid] = (tid == 0) ? -1 : 0;
    __syncthreads();

    float creg[25];
#pragma unroll
    for (int c = 0; c < 25; c++) {
        int n = c * 1024 + tid;
        creg[c] = (n < NN) ? sc[n] : -1.0f;
    }
#pragma unroll
    for (int c = 0; c < 25; c++) {
        float v = creg[c];
        if (v > CONF_T) atomicAdd(&h[__float_as_uint(v) >> 19], 1u);
    }
    __syncthreads();

    unsigned ps = h[2 * tid] + h[2 * tid + 1];
    unsigned s = ps;
#pragma unroll
    for (int off = 1; off < 32; off <<= 1) {
        unsigned v = __shfl_down_sync(0xffffffffu, s, off);
        if (lane + off < 32) s += v;
    }
    if (lane == 0) wsc[wid] = s;
    __syncthreads();
    if (wid == 0) {
        unsigned t = wsc[lane];
#pragma unroll
        for (int off = 1; off < 32; off <<= 1) {
            unsigned v = __shfl_down_sync(0xffffffffu, t, off);
            if (lane + off < 32) t += v;
        }
        unsigned tail = __shfl_down_sync(0xffffffffu, t, 1);
        if (lane == 31) tail = 0;
        wsc[32 + lane] = tail;
    }
    __syncthreads();
    unsigned S = s + wsc[32 + wid];
    unsigned Snext = S - ps;
    if (Snext + h[2 * tid + 1] >= KK) atomicMax(&ctrl[0], 2 * tid + 1);
    else if (S >= KK)                 atomicMax(&ctrl[0], 2 * tid);
    __syncthreads();
    unsigned T = (unsigned)(ctrl[0] < 0 ? 0 : ctrl[0]);

#pragma unroll
    for (int c = 0; c < 25; c++) {
        float v = creg[c];
        if (v > CONF_T) {
            unsigned bits = __float_as_uint(v);
            if ((bits >> 19) >= T) {
                int p = atomicAdd(&ctrl[2], 1);
                if (p < 8192) {
                    unsigned n = (unsigned)(c * 1024 + tid);
                    cand[p] = ((unsigned long long)bits << 32)
                            | (unsigned long long)(0xFFFFFFFFu - n);
                }
            }
        }
    }
    __syncthreads();
    int cnt = ctrl[2]; if (cnt > 8192) cnt = 8192;

    if (cnt <= 2048) {
        for (int p = cnt + tid; p < 2048; p += 1024) cand[p] = 0ull;
        __syncthreads();
        unsigned long long va = cand[tid], vb = cand[tid + 1024];
#pragma unroll
        for (int k = 2; k <= 32; k <<= 1) {
#pragma unroll
            for (int j = k >> 1; j >= 1; j >>= 1) {
                bool lower = (tid & j) == 0;
                {
                    unsigned long long pa = __shfl_xor_sync(0xffffffffu, va, j);
                    bool dir = (tid & k) == 0;
                    va = (((dir == lower) ? (va > pa) : (va < pa))) ? va : pa;
                }
                {
                    unsigned long long pb2 = __shfl_xor_sync(0xffffffffu, vb, j);
                    bool dir = ((tid + 1024) & k) == 0;
                    vb = (((dir == lower) ? (vb > pb2) : (vb < pb2))) ? vb : pb2;
                }
            }
        }
        cand[tid] = va; cand[tid + 1024] = vb;
        __syncthreads();
        for (int k = 64; k <= 2048; k <<= 1) {
            for (int j = k >> 1; j >= 32; j >>= 1) {
                for (int t2 = tid; t2 < 2048; t2 += 1024) {
                    int ixj = t2 ^ j;
                    if (ixj > t2) {
                        unsigned long long a = cand[t2], c2 = cand[ixj];
                        if (((t2 & k) == 0) ? (a < c2) : (a > c2)) { cand[t2] = c2; cand[ixj] = a; }
                    }
                }
                __syncthreads();
            }
            va = cand[tid]; vb = cand[tid + 1024];
#pragma unroll
            for (int j = 16; j >= 1; j >>= 1) {
                bool lower = (tid & j) == 0;
                {
                    unsigned long long pa = __shfl_xor_sync(0xffffffffu, va, j);
                    bool dir = (tid & k) == 0;
                    va = (((dir == lower) ? (va > pa) : (va < pa))) ? va : pa;
                }
                {
                    unsigned long long pb2 = __shfl_xor_sync(0xffffffffu, vb, j);
                    bool dir = ((tid + 1024) & k) == 0;
                    vb = (((dir == lower) ? (vb > pb2) : (vb < pb2))) ? vb : pb2;
                }
            }
            cand[tid] = va; cand[tid + 1024] = vb;
            __syncthreads();
        }
    } else {
        int n2 = 2048; while (n2 < cnt) n2 <<= 1;
        for (int p = cnt + tid; p < n2; p += 1024) cand[p] = 0ull;
        __syncthreads();
        for (int k = 2; k <= n2; k <<= 1) {
            for (int j = k >> 1; j > 0; j >>= 1) {
                for (int t2 = tid; t2 < n2; t2 += 1024) {
                    int ixj = t2 ^ j;
                    if (ixj > t2) {
                        unsigned long long a = cand[t2], c2 = cand[ixj];
                        if (((t2 & k) == 0) ? (a < c2) : (a > c2)) { cand[t2] = c2; cand[ixj] = a; }
                    }
                }
                __syncthreads();
            }
        }
    }

    {
        unsigned long long key = cand[tid];
        unsigned sbits = (unsigned)(key >> 32);
        float score; int n;
        if (sbits) { score = __uint_as_float(sbits); n = (int)(0xFFFFFFFFu - (unsigned)key); }
        else       { score = -1.0f; n = 0; }
        const float* pr = pred + ((size_t)b * NN + n) * 25;
        float x = pr[0], y = pr[1], w = pr[2], h2 = pr[3];
        float hw = __fmul_rn(w, 0.5f), hh = __fmul_rn(h2, 0.5f);
        int idx = b * KK + tid;
        g_tbox[idx] = make_float4(__fsub_rn(x, hw), __fsub_rn(y, hh),
                                  __fadd_rn(x, hw), __fadd_rn(y, hh));
        g_tsc[idx]  = score;
        g_tlb[idx]  = (int)g_lab[(size_t)b * NN + n];
    }
}

// ---------- kernel B2: pairwise IoU -> TRANSPOSED mask (branch-free hot loop) ----------
// Block (bx, b): wp = bx>>1 pairs strips (wp, 31-wp); jh = bx&1 takes alternating 256-wide
// j-chunks. Hot loop: packed float4 LDS, FFMA margin compare, predicated bit sets; the rare
// |d|<=marg band is fixed afterward with reference-order den + IEEE div (exact decisions).
__global__ void k_iou() {
    __shared__ float4 sbox[64];
    __shared__ float  sar [64];
    int b = blockIdx.y, bx = blockIdx.x, tid = threadIdx.x;
    int wp = bx >> 1, jh = bx & 1;

    if (tid < 64) {
        int strip = (tid < 32) ? wp : (31 - wp);
        int i = strip * 32 + (tid & 31);
        float4 bxv = g_tbox[b * KK + i];
        float off = __fmul_rn((float)g_tlb[b * KK + i], 4096.0f);
        // offsets applied BEFORE area: fp32 quantization at +label*4096 must match ref
        float ox1 = __fadd_rn(bxv.x, off), oy1 = __fadd_rn(bxv.y, off);
        float ox2 = __fadd_rn(bxv.z, off), oy2 = __fadd_rn(bxv.w, off);
        sbox[tid] = make_float4(ox1, oy1, ox2, oy2);
        sar[tid]  = __fmul_rn(__fsub_rn(ox2, ox1), __fsub_rn(oy2, oy1));
    }
    __syncthreads();

#pragma unroll
    for (int half = 0; half < 2; half++) {
        int w = half ? (31 - wp) : wp;
        int sbase = half * 32;
        for (int j = 32 * w + jh * 256 + tid; j < 1024; j += 512) {
            float4 bxv = g_tbox[b * KK + j];
            float off = __fmul_rn((float)g_tlb[b * KK + j], 4096.0f);
            float jx1 = __fadd_rn(bxv.x, off), jy1 = __fadd_rn(bxv.y, off);
            float jx2 = __fadd_rn(bxv.z, off), jy2 = __fadd_rn(bxv.w, off);
            float aj  = __fmul_rn(__fsub_rn(jx2, jx1), __fsub_rn(jy2, jy1));
            float ajeps = __fadd_rn(aj, 1e-9f);      // fast-path reassociation
            int top = j - 32 * w; if (top > 32) top = 32;
            unsigned bits = 0, band = 0;

            if (top == 32) {
                // full word: fixed 32-iteration unroll, immediate masks, no loop overhead
#pragma unroll
                for (int bi = 0; bi < 32; bi++) {
                    float4 ib = sbox[sbase + bi];    // LDS.128 broadcast
                    float ai  = sar[sbase + bi];
                    float ltx = fmaxf(jx1, ib.x), lty = fmaxf(jy1, ib.y);
                    float rbx = fminf(jx2, ib.z), rby = fminf(jy2, ib.w);
                    float ww = fmaxf(__fsub_rn(rbx, ltx), 0.0f);
                    float hh = fmaxf(__fsub_rn(rby, lty), 0.0f);
                    float inter = __fmul_rn(ww, hh);
                    float den = __fsub_rn(__fadd_rn(ai, ajeps), inter);
                    float d   = __fmaf_rn(-IOU_T, den, inter);
                    float marg = __fmul_rn(den, 1e-4f);
                    if (d > 0.0f)          bits |= (1u << bi);
                    if (fabsf(d) <= marg)  band |= (1u << bi);
                }
            } else {
                for (int bi = 0; bi < top; bi++) {
                    float4 ib = sbox[sbase + bi];
                    float ai  = sar[sbase + bi];
                    float ltx = fmaxf(jx1, ib.x), lty = fmaxf(jy1, ib.y);
                    float rbx = fminf(jx2, ib.z), rby = fminf(jy2, ib.w);
                    float ww = fmaxf(__fsub_rn(rbx, ltx), 0.0f);
                    float hh = fmaxf(__fsub_rn(rby, lty), 0.0f);
                    float inter = __fmul_rn(ww, hh);
                    float den = __fsub_rn(__fadd_rn(ai, ajeps), inter);
                    float d   = __fmaf_rn(-IOU_T, den, inter);
                    float marg = __fmul_rn(den, 1e-4f);
                    if (d > 0.0f)          bits |= (1u << bi);
                    if (fabsf(d) <= marg)  band |= (1u << bi);
                }
            }

            // rare exact fix-up: reference-order den + IEEE div decides band pairs
            while (band) {
                int bi = __ffs(band) - 1;
                band &= band - 1;
                unsigned m = 1u << bi;
                float4 ib = sbox[sbase + bi];
                float ai  = sar[sbase + bi];
                float ltx = fmaxf(jx1, ib.x), lty = fmaxf(jy1, ib.y);
                float rbx = fminf(jx2, ib.z), rby = fminf(jy2, ib.w);
                float ww = fmaxf(__fsub_rn(rbx, ltx), 0.0f);
                float hh = fmaxf(__fsub_rn(rby, lty), 0.0f);
                float inter = __fmul_rn(ww, hh);
                float den = __fadd_rn(__fsub_rn(__fadd_rn(ai, aj), inter), 1e-9f);
                bool sup = (inter / den) > IOU_T;
                bits = sup ? (bits | m) : (bits & ~m);
            }

            if (top > 0) g_msk[(size_t)b * 32768 + w * 1024 + j] = bits;  // coalesced over j
        }
    }
}

// ---------- kernel B3: Jacobi-fixpoint greedy NMS + clip/filter + top-300 compaction ----------
__global__ void __launch_bounds__(1024, 1) k_nms(const int* __restrict__ imw, const int* __restrict__ imh,
                      float* __restrict__ out) {
    extern __shared__ unsigned sh[];
    unsigned* cm    = sh;                    // 32768 words, [w][j] (lower triangle valid)
    unsigned* kwsA  = sh + 32768;            // 32
    unsigned* kwsB  = sh + 32800;            // 32
    unsigned* wcnt  = sh + 32832;            // 32
    unsigned* wbal  = sh + 32864;            // 32
    int*      ctrl  = (int*)(sh + 32896);    // 4
    float4*   cbox  = (float4*)(sh + 32900); // 300 (32900*4 % 16 == 0)
    float*    cscore = (float*)(cbox + MAXDET);
    int*      clabel = (int*)(cscore + MAXDET);

    int b = blockIdx.x, tid = threadIdx.x;
    int lane = tid & 31, wid = tid >> 5;

    for (int base = tid * 4; base < 32768; base += 4096) {
        int w = base >> 10, j0 = base & 1023;
        if (w <= (j0 >> 5))
            *(uint4*)(cm + base) = *(const uint4*)(g_msk + (size_t)b * 32768 + base);
    }
    float score = g_tsc[b * KK + tid];
    bool cnd = score > CONF_T;
    unsigned cbal = __ballot_sync(0xffffffffu, cnd);
    if (lane == 0) kwsA[wid] = cbal;
    __syncthreads();

    unsigned* cur = kwsA;
    unsigned* nxt = kwsB;
    unsigned mself = cm[wid * 1024 + tid] & ((1u << lane) - 1u);
    for (int it = 0; it < 1025; it++) {
        unsigned sup = mself & cur[wid];
        for (int w = 0; w < wid; w++)
            sup |= cm[w * 1024 + tid] & cur[w];
        bool nk = cnd && (sup == 0u);
        unsigned nb = __ballot_sync(0xffffffffu, nk);
        if (lane == 0) nxt[wid] = nb;
        int changed = __syncthreads_or((int)(nb != cur[wid]));
        if (!changed) break;
        unsigned* t = cur; cur = nxt; nxt = t;
    }

    bool keep = (cur[wid] >> lane) & 1u;
    float fw = (float)(*imw), fh = (float)(*imh);
    float4 bx = g_tbox[b * KK + tid];
    float x1c = fminf(fmaxf(bx.x, 0.0f), fw);
    float y1c = fminf(fmaxf(bx.y, 0.0f), fh);
    float x2c = fminf(fmaxf(bx.z, 0.0f), fw);
    float y2c = fminf(fmaxf(bx.w, 0.0f), fh);
    float bw  = __fsub_rn(x2c, x1c);
    float bh2 = __fsub_rn(y2c, y1c);
    bool valid = keep && (bw > 0.0f) && (bh2 > 0.0f) && (bw >= 1.0f) && (bh2 >= 1.0f);

    unsigned vb = __ballot_sync(0xffffffffu, valid);
    if (lane == 0) { wcnt[wid] = __popc(vb); wbal[wid] = vb; }
    __syncthreads();
    if (tid == 0) {
        int acc2 = 0;
        for (int q = 0; q < 32; q++) { int c = wcnt[q]; wcnt[q] = acc2; acc2 += c; }
        ctrl[0] = acc2;
    }
    __syncthreads();
    if (valid) {
        int rank = wcnt[wid] + __popc(wbal[wid] & ((1u << lane) - 1u));
        if (rank < MAXDET) {
            cbox[rank]   = make_float4(x1c, y1c, x2c, y2c);
            cscore[rank] = score;
            clabel[rank] = g_tlb[b * KK + tid];
        }
    }
    __syncthreads();

    int total = ctrl[0]; if (total > MAXDET) total = MAXDET;
    if (tid < MAXDET) {
        float4 ob; float os, ol, ov;
        if (tid < total) { ob = cbox[tid]; os = cscore[tid]; ol = (float)clabel[tid]; ov = 1.0f; }
        else             { ob = make_float4(0, 0, 0, 0); os = 0.0f; ol = 0.0f; ov = 0.0f; }
        float* obox = out + ((size_t)b * MAXDET + tid) * 4;
        obox[0] = ob.x; obox[1] = ob.y; obox[2] = ob.z; obox[3] = ob.w;
        out[BB * MAXDET * 4 + b * MAXDET + tid] = os;   // det_scores
        out[BB * MAXDET * 5 + b * MAXDET + tid] = ol;   // det_labels (as f32)
        out[BB * MAXDET * 6 + b * MAXDET + tid] = ov;   // vm (as f32)
    }
}

extern "C" void kernel_launch(void* const* d_in, const int* in_sizes, int n_in,
                              void* d_out, int out_size) {
    const float* pred = (const float*)d_in[0];
    const int*   imh  = (const int*)d_in[1];
    const int*   imw  = (const int*)d_in[2];
    float* out = (float*)d_out;

    cudaFuncSetAttribute((const void*)k_topk,
                         cudaFuncAttributeMaxDynamicSharedMemorySize, 74048);
    cudaFuncSetAttribute((const void*)k_nms,
                         cudaFuncAttributeMaxDynamicSharedMemorySize, 138800);

    // 2-way k_score split keeps total work identical and places k_iou at the
    // profiler's capture slot (#4) to verify the instruction-diet fix.
    k_score<<<1575, 256>>>(pred, 0);
    k_score<<<1575, 256>>>(pred, 1575);
    k_topk<<<BB, 1024, 74048>>>(pred);
    k_iou<<<dim3(32, BB), 256>>>();
    k_nms<<<BB, 1024, 138800>>>(imw, imh, out);
}

// round 14
// speedup vs baseline: 1.3392x; 1.1104x over previous
#include <cuda_runtime.h>
#include <cstdint>
#include <cstddef>

#define BB 32
#define NN 25200
#define NCC 20
#define KK 1024
#define MAXDET 300
#define CONF_T 0.001f
#define IOU_T 0.45f

// ---------- scratch (static device allocations; no cudaMalloc) ----------
__device__ float         g_conf[BB * NN];
__device__ unsigned char g_lab [BB * NN];
__device__ float4        g_tbox[BB * KK];
__device__ float         g_tsc [BB * KK];
__device__ int           g_tlb [BB * KK];
__device__ unsigned      g_msk [BB * KK * 32];   // TRANSPOSED mask: [b][w*1024+j], bit bi => i=32w+bi suppresses j (i<j)

// ---------- kernel A: scores + argmax labels (grid-parallel DRAM stream; 2 sub-launches) ----------
__global__ void k_score(const float* __restrict__ pred, int blockOff) {
    __shared__ float s[256 * 25];
    int blk = blockOff + blockIdx.x;
    size_t base4 = (size_t)blk * 1600;                  // 6400 floats = 1600 float4
    const float4* p4 = (const float4*)pred + base4;
    float4* s4 = (float4*)s;
    for (int k = threadIdx.x; k < 1600; k += 256) s4[k] = p4[k];
    __syncthreads();
    const float* row = s + threadIdx.x * 25;
    float obj  = row[4];
    float best = row[5];
    int   bl   = 0;
#pragma unroll
    for (int c = 1; c < NCC; c++) {
        float v = row[5 + c];
        if (v > best) { best = v; bl = c; }             // first-max like jnp.argmax
    }
    float conf = __fmul_rn(obj, best);
    size_t r = (size_t)blk * 256 + threadIdx.x;
    g_conf[r] = conf;
    g_lab[r]  = (unsigned char)bl;
}

// ---------- kernel B1: exact stable top-1024 per batch (R10 monolith, register-batched) ----------
__global__ void __launch_bounds__(1024, 1) k_topk(const float* __restrict__ pred) {
    extern __shared__ unsigned sh[];
    unsigned long long* cand = (unsigned long long*)sh;  // 8192 keys (64 KB)
    unsigned* h    = sh + 16384;          // 2048 bucket counts (bits>>19)
    int*      ctrl = (int*)(sh + 18432);  // 16: [0]=T(bucket) [2]=cnt
    unsigned* wsc  = sh + 18448;          // 64: warp totals + tails

    int b = blockIdx.x;
    int tid = threadIdx.x;
    int lane = tid & 31, wid = tid >> 5;
    const float* sc = g_conf + (size_t)b * NN;

    h[tid] = 0; h[tid + 1024] = 0;
    if (tid < 16) ctrl[tid] = (tid == 0) ? -1 : 0;
    __syncthreads();

    float creg[25];
#pragma unroll
    for (int c = 0; c < 25; c++) {
        int n = c * 1024 + tid;
        creg[c] = (n < NN) ? sc[n] : -1.0f;
    }
#pragma unroll
    for (int c = 0; c < 25; c++) {
        float v = creg[c];
        if (v > CONF_T) atomicAdd(&h[__float_as_uint(v) >> 19], 1u);
    }
    __syncthreads();

    unsigned ps = h[2 * tid] + h[2 * tid + 1];
    unsigned s = ps;
#pragma unroll
    for (int off = 1; off < 32; off <<= 1) {
        unsigned v = __shfl_down_sync(0xffffffffu, s, off);
        if (lane + off < 32) s += v;
    }
    if (lane == 0) wsc[wid] = s;
    __syncthreads();
    if (wid == 0) {
        unsigned t = wsc[lane];
#pragma unroll
        for (int off = 1; off < 32; off <<= 1) {
            unsigned v = __shfl_down_sync(0xffffffffu, t, off);
            if (lane + off < 32) t += v;
        }
        unsigned tail = __shfl_down_sync(0xffffffffu, t, 1);
        if (lane == 31) tail = 0;
        wsc[32 + lane] = tail;
    }
    __syncthreads();
    unsigned S = s + wsc[32 + wid];
    unsigned Snext = S - ps;
    if (Snext + h[2 * tid + 1] >= KK) atomicMax(&ctrl[0], 2 * tid + 1);
    else if (S >= KK)                 atomicMax(&ctrl[0], 2 * tid);
    __syncthreads();
    unsigned T = (unsigned)(ctrl[0] < 0 ? 0 : ctrl[0]);

#pragma unroll
    for (int c = 0; c < 25; c++) {
        float v = creg[c];
        if (v > CONF_T) {
            unsigned bits = __float_as_uint(v);
            if ((bits >> 19) >= T) {
                int p = atomicAdd(&ctrl[2], 1);
                if (p < 8192) {
                    unsigned n = (unsigned)(c * 1024 + tid);
                    cand[p] = ((unsigned long long)bits << 32)
                            | (unsigned long long)(0xFFFFFFFFu - n);
                }
            }
        }
    }
    __syncthreads();
    int cnt = ctrl[2]; if (cnt > 8192) cnt = 8192;

    if (cnt <= 2048) {
        for (int p = cnt + tid; p < 2048; p += 1024) cand[p] = 0ull;
        __syncthreads();
        unsigned long long va = cand[tid], vb = cand[tid + 1024];
#pragma unroll
        for (int k = 2; k <= 32; k <<= 1) {
#pragma unroll
            for (int j = k >> 1; j >= 1; j >>= 1) {
                bool lower = (tid & j) == 0;
                {
                    unsigned long long pa = __shfl_xor_sync(0xffffffffu, va, j);
                    bool dir = (tid & k) == 0;
                    va = (((dir == lower) ? (va > pa) : (va < pa))) ? va : pa;
                }
                {
                    unsigned long long pb2 = __shfl_xor_sync(0xffffffffu, vb, j);
                    bool dir = ((tid + 1024) & k) == 0;
                    vb = (((dir == lower) ? (vb > pb2) : (vb < pb2))) ? vb : pb2;
                }
            }
        }
        cand[tid] = va; cand[tid + 1024] = vb;
        __syncthreads();
        for (int k = 64; k <= 2048; k <<= 1) {
            for (int j = k >> 1; j >= 32; j >>= 1) {
                for (int t2 = tid; t2 < 2048; t2 += 1024) {
                    int ixj = t2 ^ j;
                    if (ixj > t2) {
                        unsigned long long a = cand[t2], c2 = cand[ixj];
                        if (((t2 & k) == 0) ? (a < c2) : (a > c2)) { cand[t2] = c2; cand[ixj] = a; }
                    }
                }
                __syncthreads();
            }
            va = cand[tid]; vb = cand[tid + 1024];
#pragma unroll
            for (int j = 16; j >= 1; j >>= 1) {
                bool lower = (tid & j) == 0;
                {
                    unsigned long long pa = __shfl_xor_sync(0xffffffffu, va, j);
                    bool dir = (tid & k) == 0;
                    va = (((dir == lower) ? (va > pa) : (va < pa))) ? va : pa;
                }
                {
                    unsigned long long pb2 = __shfl_xor_sync(0xffffffffu, vb, j);
                    bool dir = ((tid + 1024) & k) == 0;
                    vb = (((dir == lower) ? (vb > pb2) : (vb < pb2))) ? vb : pb2;
                }
            }
            cand[tid] = va; cand[tid + 1024] = vb;
            __syncthreads();
        }
    } else {
        int n2 = 2048; while (n2 < cnt) n2 <<= 1;
        for (int p = cnt + tid; p < n2; p += 1024) cand[p] = 0ull;
        __syncthreads();
        for (int k = 2; k <= n2; k <<= 1) {
            for (int j = k >> 1; j > 0; j >>= 1) {
                for (int t2 = tid; t2 < n2; t2 += 1024) {
                    int ixj = t2 ^ j;
                    if (ixj > t2) {
                        unsigned long long a = cand[t2], c2 = cand[ixj];
                        if (((t2 & k) == 0) ? (a < c2) : (a > c2)) { cand[t2] = c2; cand[ixj] = a; }
                    }
                }
                __syncthreads();
            }
        }
    }

    {
        unsigned long long key = cand[tid];
        unsigned sbits = (unsigned)(key >> 32);
        float score; int n;
        if (sbits) { score = __uint_as_float(sbits); n = (int)(0xFFFFFFFFu - (unsigned)key); }
        else       { score = -1.0f; n = 0; }
        const float* pr = pred + ((size_t)b * NN + n) * 25;
        float x = pr[0], y = pr[1], w = pr[2], h2 = pr[3];
        float hw = __fmul_rn(w, 0.5f), hh = __fmul_rn(h2, 0.5f);
        int idx = b * KK + tid;
        g_tbox[idx] = make_float4(__fsub_rn(x, hw), __fsub_rn(y, hh),
                                  __fadd_rn(x, hw), __fadd_rn(y, hh));
        g_tsc[idx]  = score;
        g_tlb[idx]  = (int)g_lab[(size_t)b * NN + n];
    }
}

// ---------- kernel B2: pairwise IoU -> TRANSPOSED mask (branch-free, reg-capped) ----------
// Block (bx, b): wp = bx>>1 pairs strips (wp, 31-wp); jh = bx&1 takes alternating 256-wide
// j-chunks. __launch_bounds__(256,6) caps regs at 42 -> high occupancy WITH the slim loop.
// Hot loop: float4 LDS broadcast + FFMA margin compare, partial unroll 4. Rare band pairs
// fixed afterward with reference-order den + IEEE div (exact decisions).
__global__ void __launch_bounds__(256, 6) k_iou() {
    __shared__ float4 sbox[64];
    __shared__ float  sar [64];
    int b = blockIdx.y, bx = blockIdx.x, tid = threadIdx.x;
    int wp = bx >> 1, jh = bx & 1;

    if (tid < 64) {
        int strip = (tid < 32) ? wp : (31 - wp);
        int i = strip * 32 + (tid & 31);
        float4 bxv = g_tbox[b * KK + i];
        float off = __fmul_rn((float)g_tlb[b * KK + i], 4096.0f);
        // offsets applied BEFORE area: fp32 quantization at +label*4096 must match ref
        float ox1 = __fadd_rn(bxv.x, off), oy1 = __fadd_rn(bxv.y, off);
        float ox2 = __fadd_rn(bxv.z, off), oy2 = __fadd_rn(bxv.w, off);
        sbox[tid] = make_float4(ox1, oy1, ox2, oy2);
        sar[tid]  = __fmul_rn(__fsub_rn(ox2, ox1), __fsub_rn(oy2, oy1));
    }
    __syncthreads();

#pragma unroll
    for (int half = 0; half < 2; half++) {
        int w = half ? (31 - wp) : wp;
        int sbase = half * 32;
        for (int j = 32 * w + jh * 256 + tid; j < 1024; j += 512) {
            float4 bxv = g_tbox[b * KK + j];
            float off = __fmul_rn((float)g_tlb[b * KK + j], 4096.0f);
            float jx1 = __fadd_rn(bxv.x, off), jy1 = __fadd_rn(bxv.y, off);
            float jx2 = __fadd_rn(bxv.z, off), jy2 = __fadd_rn(bxv.w, off);
            float aj  = __fmul_rn(__fsub_rn(jx2, jx1), __fsub_rn(jy2, jy1));
            float ajeps = __fadd_rn(aj, 1e-9f);      // fast-path reassociation
            int top = j - 32 * w; if (top > 32) top = 32;
            unsigned bits = 0, band = 0;

#pragma unroll 4
            for (int bi = 0; bi < top; bi++) {
                float4 ib = sbox[sbase + bi];        // LDS.128 broadcast
                float ai  = sar[sbase + bi];
                float ltx = fmaxf(jx1, ib.x), lty = fmaxf(jy1, ib.y);
                float rbx = fminf(jx2, ib.z), rby = fminf(jy2, ib.w);
                float ww = fmaxf(__fsub_rn(rbx, ltx), 0.0f);
                float hh = fmaxf(__fsub_rn(rby, lty), 0.0f);
                float inter = __fmul_rn(ww, hh);
                float den = __fsub_rn(__fadd_rn(ai, ajeps), inter);
                float d   = __fmaf_rn(-IOU_T, den, inter);
                float marg = __fmul_rn(den, 1e-4f);
                if (d > 0.0f)          bits |= (1u << bi);
                if (fabsf(d) <= marg)  band |= (1u << bi);
            }

            // rare exact fix-up: reference-order den + IEEE div decides band pairs
            while (band) {
                int bi = __ffs(band) - 1;
                band &= band - 1;
                unsigned m = 1u << bi;
                float4 ib = sbox[sbase + bi];
                float ai  = sar[sbase + bi];
                float ltx = fmaxf(jx1, ib.x), lty = fmaxf(jy1, ib.y);
                float rbx = fminf(jx2, ib.z), rby = fminf(jy2, ib.w);
                float ww = fmaxf(__fsub_rn(rbx, ltx), 0.0f);
                float hh = fmaxf(__fsub_rn(rby, lty), 0.0f);
                float inter = __fmul_rn(ww, hh);
                float den = __fadd_rn(__fsub_rn(__fadd_rn(ai, aj), inter), 1e-9f);
                bool sup = (inter / den) > IOU_T;
                bits = sup ? (bits | m) : (bits & ~m);
            }

            if (top > 0) g_msk[(size_t)b * 32768 + w * 1024 + j] = bits;  // coalesced over j
        }
    }
}

// ---------- kernel B3: Jacobi-fixpoint greedy NMS + clip/filter + top-300 compaction ----------
__global__ void __launch_bounds__(1024, 1) k_nms(const int* __restrict__ imw, const int* __restrict__ imh,
                      float* __restrict__ out) {
    extern __shared__ unsigned sh[];
    unsigned* cm    = sh;                    // 32768 words, [w][j] (lower triangle valid)
    unsigned* kwsA  = sh + 32768;            // 32
    unsigned* kwsB  = sh + 32800;            // 32
    unsigned* wcnt  = sh + 32832;            // 32
    unsigned* wbal  = sh + 32864;            // 32
    int*      ctrl  = (int*)(sh + 32896);    // 4
    float4*   cbox  = (float4*)(sh + 32900); // 300 (32900*4 % 16 == 0)
    float*    cscore = (float*)(cbox + MAXDET);
    int*      clabel = (int*)(cscore + MAXDET);

    int b = blockIdx.x, tid = threadIdx.x;
    int lane = tid & 31, wid = tid >> 5;

    for (int base = tid * 4; base < 32768; base += 4096) {
        int w = base >> 10, j0 = base & 1023;
        if (w <= (j0 >> 5))
            *(uint4*)(cm + base) = *(const uint4*)(g_msk + (size_t)b * 32768 + base);
    }
    float score = g_tsc[b * KK + tid];
    bool cnd = score > CONF_T;
    unsigned cbal = __ballot_sync(0xffffffffu, cnd);
    if (lane == 0) kwsA[wid] = cbal;
    __syncthreads();

    unsigned* cur = kwsA;
    unsigned* nxt = kwsB;
    unsigned mself = cm[wid * 1024 + tid] & ((1u << lane) - 1u);
    for (int it = 0; it < 1025; it++) {
        unsigned sup = mself & cur[wid];
        for (int w = 0; w < wid; w++)
            sup |= cm[w * 1024 + tid] & cur[w];
        bool nk = cnd && (sup == 0u);
        unsigned nb = __ballot_sync(0xffffffffu, nk);
        if (lane == 0) nxt[wid] = nb;
        int changed = __syncthreads_or((int)(nb != cur[wid]));
        if (!changed) break;
        unsigned* t = cur; cur = nxt; nxt = t;
    }

    bool keep = (cur[wid] >> lane) & 1u;
    float fw = (float)(*imw), fh = (float)(*imh);
    float4 bx = g_tbox[b * KK + tid];
    float x1c = fminf(fmaxf(bx.x, 0.0f), fw);
    float y1c = fminf(fmaxf(bx.y, 0.0f), fh);
    float x2c = fminf(fmaxf(bx.z, 0.0f), fw);
    float y2c = fminf(fmaxf(bx.w, 0.0f), fh);
    float bw  = __fsub_rn(x2c, x1c);
    float bh2 = __fsub_rn(y2c, y1c);
    bool valid = keep && (bw > 0.0f) && (bh2 > 0.0f) && (bw >= 1.0f) && (bh2 >= 1.0f);

    unsigned vb = __ballot_sync(0xffffffffu, valid);
    if (lane == 0) { wcnt[wid] = __popc(vb); wbal[wid] = vb; }
    __syncthreads();
    if (tid == 0) {
        int acc2 = 0;
        for (int q = 0; q < 32; q++) { int c = wcnt[q]; wcnt[q] = acc2; acc2 += c; }
        ctrl[0] = acc2;
    }
    __syncthreads();
    if (valid) {
        int rank = wcnt[wid] + __popc(wbal[wid] & ((1u << lane) - 1u));
        if (rank < MAXDET) {
            cbox[rank]   = make_float4(x1c, y1c, x2c, y2c);
            cscore[rank] = score;
            clabel[rank] = g_tlb[b * KK + tid];
        }
    }
    __syncthreads();

    int total = ctrl[0]; if (total > MAXDET) total = MAXDET;
    if (tid < MAXDET) {
        float4 ob; float os, ol, ov;
        if (tid < total) { ob = cbox[tid]; os = cscore[tid]; ol = (float)clabel[tid]; ov = 1.0f; }
        else             { ob = make_float4(0, 0, 0, 0); os = 0.0f; ol = 0.0f; ov = 0.0f; }
        float* obox = out + ((size_t)b * MAXDET + tid) * 4;
        obox[0] = ob.x; obox[1] = ob.y; obox[2] = ob.z; obox[3] = ob.w;
        out[BB * MAXDET * 4 + b * MAXDET + tid] = os;   // det_scores
        out[BB * MAXDET * 5 + b * MAXDET + tid] = ol;   // det_labels (as f32)
        out[BB * MAXDET * 6 + b * MAXDET + tid] = ov;   // vm (as f32)
    }
}

extern "C" void kernel_launch(void* const* d_in, const int* in_sizes, int n_in,
                              void* d_out, int out_size) {
    const float* pred = (const float*)d_in[0];
    const int*   imh  = (const int*)d_in[1];
    const int*   imw  = (const int*)d_in[2];
    float* out = (float*)d_out;

    cudaFuncSetAttribute((const void*)k_topk,
                         cudaFuncAttributeMaxDynamicSharedMemorySize, 74048);
    cudaFuncSetAttribute((const void*)k_nms,
                         cudaFuncAttributeMaxDynamicSharedMemorySize, 138800);

    // 2-way k_score split keeps total work identical and places k_iou at the
    // profiler's capture slot (#4) to verify the reg-cap fix.
    k_score<<<1575, 256>>>(pred, 0);
    k_score<<<1575, 256>>>(pred, 1575);
    k_topk<<<BB, 1024, 74048>>>(pred);
    k_iou<<<dim3(32, BB), 256>>>();
    k_nms<<<BB, 1024, 138800>>>(imw, imh, out);
}